// round 15
// baseline (speedup 1.0000x reference)
#include <cuda_runtime.h>

// ---------------------------------------------------------------------------
// GRU encoder-decoder, persistent per-CTA recurrence, f32x2-packed compute.
// R14 = R13 (4-unit x 2-row tiles, NT=256, rz/n split weights, tanh.approx
// epilogue) + dup-activation layout: xs/hs stored [k][64] with value(k,r) at
// floats {2r,2r+1}. Activation fetch = one LDS.128 at 16*rt giving both
// f32x2 row operands directly -- the last 2 dup-MOVs leave the fma pipe.
// Inner k-body: 1 LDS.128 act + 3 LDS.128 weights + 12 FFMA2, nothing else.
// ---------------------------------------------------------------------------

typedef unsigned long long u64;

#define Hh     64
#define G3     192
#define ROWS   32
#define NT     256
#define TSEQ   256
#define NINP   6

// SMEM float offsets
#define OFF_WX0RZ  0        // [6][128]
#define OFF_WX0N   768      // [6][64]
#define OFF_WH0RZ  1152     // [64][128]
#define OFF_WH0N   9344     // [64][64]
#define OFF_WX1RZ  13440    // [64][128]
#define OFF_WX1N   21632    // [64][64]
#define OFF_WH1RZ  25728    // [64][128]
#define OFF_WH1N   33920    // [64][64]
#define OFF_HS0    38016    // [2][64][64] dup ([k][2r])
#define OFF_HS1    46208    // [2][64][64]
#define OFF_XS     54400    // [2][8][64]
#define OFF_OW     55424    // [64]
#define OFF_OB     55488    // [1]
#define SMEM_FLOATS 55492   // 221,968 bytes

#define HBUF 4096
#define XBUF 512

__device__ __forceinline__ u64 pk2(float lo, float hi) {
    u64 r; asm("mov.b64 %0, {%1,%2};" : "=l"(r) : "f"(lo), "f"(hi)); return r;
}
__device__ __forceinline__ float2 up2(u64 v) {
    float2 r; asm("mov.b64 {%0,%1}, %2;" : "=f"(r.x), "=f"(r.y) : "l"(v)); return r;
}
#define FFMA2(acc, a, b) \
    asm("fma.rn.f32x2 %0, %1, %2, %0;" : "+l"(acc) : "l"(a), "l"(b))

__device__ __forceinline__ float tanhapx(float x) {
    float y; asm("tanh.approx.f32 %0, %1;" : "=f"(y) : "f"(x)); return y;
}
__device__ __forceinline__ float sigapx(float x) {
    return fmaf(tanhapx(0.5f * x), 0.5f, 0.5f);
}

// Split-transpose W[192][K] (row-major) into 4-unit-group layout:
//   rz[k*128 + ug*8 + (lane>>1)*4 + gate*2 + (lane&1)]   gates r(0),z(1)
//   n [k*64  + ug*4 + lane]                              gate n
__device__ __forceinline__ void load_w_split4(float* dstRZ, float* dstN,
                                              const float* __restrict__ src,
                                              int K, int tid) {
    for (int idx = tid; idx < G3 * K; idx += NT) {
        int g = idx / K;
        int k = idx - g * K;
        int gate = g >> 6;          // 0=r,1=z,2=n
        int j    = g & 63;
        int ug   = j >> 2;
        int lane = j & 3;
        float v = src[idx];
        if (gate < 2)
            dstRZ[k * 128 + ug * 8 + (lane >> 1) * 4 + gate * 2 + (lane & 1)] = v;
        else
            dstN [k * 64  + ug * 4 + lane] = v;
    }
}

// GRU cell for this thread's [4 units (2 f32x2 pairs) x 2 rows] tile.
// Activations dup layout: value(k,r) at src[k*64 + 2r + {0,1}].
template<int KIN>
__device__ __forceinline__ void gru_tile4(
    const float* __restrict__ Wxrz, const float* __restrict__ Wxn,
    const float* __restrict__ Whrz, const float* __restrict__ Whn,
    const float* __restrict__ xsrc, const float* __restrict__ hsrc,
    float* __restrict__ hdst,
    const u64 br[2], const u64 bz[2], const u64 bi[2], const u64 bh[2],
    int ug, int rt)
{
    // accum[pair][row]
    u64 ar[2][2], az[2][2], ai[2][2], ah[2][2];
#pragma unroll
    for (int p = 0; p < 2; p++)
#pragma unroll
        for (int rr = 0; rr < 2; rr++) {
            ar[p][rr] = br[p]; az[p][rr] = bz[p];
            ai[p][rr] = bi[p]; ah[p][rr] = bh[p];
        }

    const float* wxrz = Wxrz + ug * 8;
    const float* wxn  = Wxn  + ug * 4;
    const float* xp   = xsrc + 4 * rt;       // dup pairs for rows 2rt, 2rt+1
#pragma unroll
    for (int k = 0; k < KIN; k++) {
        ulonglong2 xa = *(const ulonglong2*)(xp + k * 64);          // (x0x0, x1x1)
        ulonglong2 w01 = *(const ulonglong2*)(wxrz + k * 128);      // (r01, z01)
        ulonglong2 w23 = *(const ulonglong2*)(wxrz + k * 128 + 4);  // (r23, z23)
        ulonglong2 wn2 = *(const ulonglong2*)(wxn + k * 64);        // (n01, n23)
        FFMA2(ar[0][0], w01.x, xa.x); FFMA2(ar[0][1], w01.x, xa.y);
        FFMA2(az[0][0], w01.y, xa.x); FFMA2(az[0][1], w01.y, xa.y);
        FFMA2(ar[1][0], w23.x, xa.x); FFMA2(ar[1][1], w23.x, xa.y);
        FFMA2(az[1][0], w23.y, xa.x); FFMA2(az[1][1], w23.y, xa.y);
        FFMA2(ai[0][0], wn2.x, xa.x); FFMA2(ai[0][1], wn2.x, xa.y);
        FFMA2(ai[1][0], wn2.y, xa.x); FFMA2(ai[1][1], wn2.y, xa.y);
    }

    const float* whrz = Whrz + ug * 8;
    const float* whn  = Whn  + ug * 4;
    const float* hp   = hsrc + 4 * rt;
#pragma unroll 8
    for (int k = 0; k < Hh; k++) {
        ulonglong2 ha = *(const ulonglong2*)(hp + k * 64);          // (h0h0, h1h1)
        ulonglong2 w01 = *(const ulonglong2*)(whrz + k * 128);
        ulonglong2 w23 = *(const ulonglong2*)(whrz + k * 128 + 4);
        ulonglong2 wn2 = *(const ulonglong2*)(whn + k * 64);
        FFMA2(ar[0][0], w01.x, ha.x); FFMA2(ar[0][1], w01.x, ha.y);
        FFMA2(az[0][0], w01.y, ha.x); FFMA2(az[0][1], w01.y, ha.y);
        FFMA2(ar[1][0], w23.x, ha.x); FFMA2(ar[1][1], w23.x, ha.y);
        FFMA2(az[1][0], w23.y, ha.x); FFMA2(az[1][1], w23.y, ha.y);
        FFMA2(ah[0][0], wn2.x, ha.x); FFMA2(ah[0][1], wn2.x, ha.y);
        FFMA2(ah[1][0], wn2.y, ha.x); FFMA2(ah[1][1], wn2.y, ha.y);
    }

    // epilogue: r,z sigmoid; n = tanh(in + r*hn); h' = n + z*(h_old - n)
    const int j0 = ug * 4;
    float2 ho[4];
#pragma unroll
    for (int u = 0; u < 4; u++) {
        ulonglong2 hv = *(const ulonglong2*)(hsrc + (j0 + u) * 64 + 4 * rt);
        ho[u] = make_float2(up2(hv.x).x, up2(hv.y).x);   // rows 2rt, 2rt+1
    }

    float2 onew[4];
#pragma unroll
    for (int p = 0; p < 2; p++)
#pragma unroll
        for (int rr = 0; rr < 2; rr++) {
            float2 arv = up2(ar[p][rr]), azv = up2(az[p][rr]);
            float2 aiv = up2(ai[p][rr]), ahv = up2(ah[p][rr]);
            {
                float r = sigapx(arv.x), z = sigapx(azv.x);
                float n = tanhapx(fmaf(r, ahv.x, aiv.x));
                float hold = (rr == 0) ? ho[2 * p].x : ho[2 * p].y;
                float o = fmaf(z, hold - n, n);
                if (rr == 0) onew[2 * p].x = o; else onew[2 * p].y = o;
            }
            {
                float r = sigapx(arv.y), z = sigapx(azv.y);
                float n = tanhapx(fmaf(r, ahv.y, aiv.y));
                float hold = (rr == 0) ? ho[2 * p + 1].x : ho[2 * p + 1].y;
                float o = fmaf(z, hold - n, n);
                if (rr == 0) onew[2 * p + 1].x = o; else onew[2 * p + 1].y = o;
            }
        }
#pragma unroll
    for (int u = 0; u < 4; u++)
        *(ulonglong2*)(hdst + (j0 + u) * 64 + 4 * rt) =
            make_ulonglong2(pk2(onew[u].x, onew[u].x), pk2(onew[u].y, onew[u].y));
}

extern __shared__ float sm[];

__global__ __launch_bounds__(NT, 1)
void gru_kernel(
    const float* __restrict__ x,
    const float* __restrict__ eWih0, const float* __restrict__ eWhh0,
    const float* __restrict__ ebih0, const float* __restrict__ ebhh0,
    const float* __restrict__ eWih1, const float* __restrict__ eWhh1,
    const float* __restrict__ ebih1, const float* __restrict__ ebhh1,
    const float* __restrict__ dWih0, const float* __restrict__ dWhh0,
    const float* __restrict__ dbih0, const float* __restrict__ dbhh0,
    const float* __restrict__ dWih1, const float* __restrict__ dWhh1,
    const float* __restrict__ dbih1, const float* __restrict__ dbhh1,
    const float* __restrict__ outW, const float* __restrict__ outb,
    float* __restrict__ out, int Bn, int TL)
{
    const int tid = threadIdx.x;
    const int b0  = blockIdx.x * ROWS;

    float* Wx0rz = sm + OFF_WX0RZ;  float* Wx0n = sm + OFF_WX0N;
    float* Wh0rz = sm + OFF_WH0RZ;  float* Wh0n = sm + OFF_WH0N;
    float* Wx1rz = sm + OFF_WX1RZ;  float* Wx1n = sm + OFF_WX1N;
    float* Wh1rz = sm + OFF_WH1RZ;  float* Wh1n = sm + OFF_WH1N;
    float* hs0 = sm + OFF_HS0;
    float* hs1 = sm + OFF_HS1;
    float* xs  = sm + OFF_XS;
    float* sOW = sm + OFF_OW;
    float* sOB = sm + OFF_OB;

    const int rt = tid & 15;         // row tile (rows 2rt, 2rt+1)
    const int ug = tid >> 4;         // unit group (4 units)
    const int j0 = ug * 4;

    // ---- stage encoder weights ----
    load_w_split4(Wx0rz, Wx0n, eWih0, NINP, tid);
    load_w_split4(Wh0rz, Wh0n, eWhh0, Hh, tid);
    load_w_split4(Wx1rz, Wx1n, eWih1, Hh, tid);
    load_w_split4(Wh1rz, Wh1n, eWhh1, Hh, tid);
    for (int i = tid; i < HBUF; i += NT) {
        hs0[i] = 0.0f; hs0[HBUF + i] = 0.0f;
        hs1[i] = 0.0f; hs1[HBUF + i] = 0.0f;
    }

    // ---- encoder bias pairs in registers ----
    u64 e0r[2], e0z[2], e0i[2], e0h[2], e1r[2], e1z[2], e1i[2], e1h[2];
#pragma unroll
    for (int p = 0; p < 2; p++) {
        int jj = j0 + 2 * p;
        float2 a, b;
        a = *(const float2*)(ebih0 + jj);        b = *(const float2*)(ebhh0 + jj);
        e0r[p] = pk2(a.x + b.x, a.y + b.y);
        a = *(const float2*)(ebih0 + 64 + jj);   b = *(const float2*)(ebhh0 + 64 + jj);
        e0z[p] = pk2(a.x + b.x, a.y + b.y);
        a = *(const float2*)(ebih0 + 128 + jj);  e0i[p] = pk2(a.x, a.y);
        b = *(const float2*)(ebhh0 + 128 + jj);  e0h[p] = pk2(b.x, b.y);
        a = *(const float2*)(ebih1 + jj);        b = *(const float2*)(ebhh1 + jj);
        e1r[p] = pk2(a.x + b.x, a.y + b.y);
        a = *(const float2*)(ebih1 + 64 + jj);   b = *(const float2*)(ebhh1 + 64 + jj);
        e1z[p] = pk2(a.x + b.x, a.y + b.y);
        a = *(const float2*)(ebih1 + 128 + jj);  e1i[p] = pk2(a.x, a.y);
        b = *(const float2*)(ebhh1 + 128 + jj);  e1h[p] = pk2(b.x, b.y);
    }

    // prestage x for t=0 into buffer 0 (dup layout)
    const int xi = tid >> 5, xr = tid & 31;
    if (tid < NINP * ROWS) {
        float v = (b0 + xr < Bn)
            ? x[(size_t)(b0 + xr) * (TSEQ * NINP) + xi] : 0.0f;
        *(u64*)(xs + xi * 64 + 2 * xr) = pk2(v, v);
    }
    __syncthreads();

    // ---- encoder: 256 steps ----
    int cur = 0;
    for (int t = 0; t < TSEQ; t++) {
        float xreg = 0.0f;
        if (tid < NINP * ROWS && t + 1 < TSEQ && b0 + xr < Bn)
            xreg = x[(size_t)(b0 + xr) * (TSEQ * NINP) + (size_t)(t + 1) * NINP + xi];
        int nxt = cur ^ 1;
        gru_tile4<NINP>(Wx0rz, Wx0n, Wh0rz, Wh0n,
                        xs + cur * XBUF, hs0 + cur * HBUF, hs0 + nxt * HBUF,
                        e0r, e0z, e0i, e0h, ug, rt);
        if (tid < NINP * ROWS)
            *(u64*)(xs + nxt * XBUF + xi * 64 + 2 * xr) = pk2(xreg, xreg);
        __syncthreads();
        gru_tile4<Hh>(Wx1rz, Wx1n, Wh1rz, Wh1n,
                      hs0 + nxt * HBUF, hs1 + cur * HBUF, hs1 + nxt * HBUF,
                      e1r, e1z, e1i, e1h, ug, rt);
        cur = nxt;
        __syncthreads();
    }

    // ---- swap in decoder weights ----
    load_w_split4(Wx0rz, Wx0n, dWih0, 1, tid);
    load_w_split4(Wh0rz, Wh0n, dWhh0, Hh, tid);
    load_w_split4(Wx1rz, Wx1n, dWih1, Hh, tid);
    load_w_split4(Wh1rz, Wh1n, dWhh1, Hh, tid);
    if (tid < Hh) sOW[tid] = outW[tid];
    if (tid == 0) sOB[0] = outb[0];
    if (tid < ROWS) *(u64*)(xs + 2 * tid) = pk2(0.0f, 0.0f);   // prev cv = 0
#pragma unroll
    for (int p = 0; p < 2; p++) {
        int jj = j0 + 2 * p;
        float2 a, b;
        a = *(const float2*)(dbih0 + jj);        b = *(const float2*)(dbhh0 + jj);
        e0r[p] = pk2(a.x + b.x, a.y + b.y);
        a = *(const float2*)(dbih0 + 64 + jj);   b = *(const float2*)(dbhh0 + 64 + jj);
        e0z[p] = pk2(a.x + b.x, a.y + b.y);
        a = *(const float2*)(dbih0 + 128 + jj);  e0i[p] = pk2(a.x, a.y);
        b = *(const float2*)(dbhh0 + 128 + jj);  e0h[p] = pk2(b.x, b.y);
        a = *(const float2*)(dbih1 + jj);        b = *(const float2*)(dbhh1 + jj);
        e1r[p] = pk2(a.x + b.x, a.y + b.y);
        a = *(const float2*)(dbih1 + 64 + jj);   b = *(const float2*)(dbhh1 + 64 + jj);
        e1z[p] = pk2(a.x + b.x, a.y + b.y);
        a = *(const float2*)(dbih1 + 128 + jj);  e1i[p] = pk2(a.x, a.y);
        b = *(const float2*)(dbhh1 + 128 + jj);  e1h[p] = pk2(b.x, b.y);
    }
    __syncthreads();

    // ---- decoder: TL autoregressive steps ----
    for (int s = 0; s < TL; s++) {
        int nxt = cur ^ 1;
        gru_tile4<1>(Wx0rz, Wx0n, Wh0rz, Wh0n,
                     xs, hs0 + cur * HBUF, hs0 + nxt * HBUF,
                     e0r, e0z, e0i, e0h, ug, rt);
        __syncthreads();
        gru_tile4<Hh>(Wx1rz, Wx1n, Wh1rz, Wh1n,
                      hs0 + nxt * HBUF, hs1 + cur * HBUF, hs1 + nxt * HBUF,
                      e1r, e1z, e1i, e1h, ug, rt);
        __syncthreads();
        if (tid < ROWS) {
            float acc = sOB[0];
            const float* hp = hs1 + nxt * HBUF + 2 * tid;
            #pragma unroll 8
            for (int j = 0; j < Hh; j++)
                acc = fmaf(sOW[j], hp[j * 64], acc);
            if (b0 + tid < Bn)
                out[(size_t)(b0 + tid) * TL + s] = acc;
            *(u64*)(xs + 2 * tid) = pk2(acc, acc);
        }
        cur = nxt;
        __syncthreads();
    }
}

extern "C" void kernel_launch(void* const* d_in, const int* in_sizes, int n_in,
                              void* d_out, int out_size) {
    const float* x      = (const float*)d_in[0];
    const float* eWih0  = (const float*)d_in[1];
    const float* eWhh0  = (const float*)d_in[2];
    const float* ebih0  = (const float*)d_in[3];
    const float* ebhh0  = (const float*)d_in[4];
    const float* eWih1  = (const float*)d_in[5];
    const float* eWhh1  = (const float*)d_in[6];
    const float* ebih1  = (const float*)d_in[7];
    const float* ebhh1  = (const float*)d_in[8];
    const float* dWih0  = (const float*)d_in[9];
    const float* dWhh0  = (const float*)d_in[10];
    const float* dbih0  = (const float*)d_in[11];
    const float* dbhh0  = (const float*)d_in[12];
    const float* dWih1  = (const float*)d_in[13];
    const float* dWhh1  = (const float*)d_in[14];
    const float* dbih1  = (const float*)d_in[15];
    const float* dbhh1  = (const float*)d_in[16];
    const float* outW   = (const float*)d_in[17];
    const float* outb   = (const float*)d_in[18];

    int B  = in_sizes[0] / (TSEQ * NINP);
    int TL = out_size / B;                       // 180
    int grid = (B + ROWS - 1) / ROWS;            // 128
    size_t smem = SMEM_FLOATS * sizeof(float);   // ~222 KB

    cudaFuncSetAttribute(gru_kernel,
                         cudaFuncAttributeMaxDynamicSharedMemorySize,
                         (int)smem);

    gru_kernel<<<grid, NT, smem>>>(
        x, eWih0, eWhh0, ebih0, ebhh0, eWih1, eWhh1, ebih1, ebhh1,
        dWih0, dWhh0, dbih0, dbhh0, dWih1, dWhh1, dbih1, dbhh1,
        outW, outb, (float*)d_out, B, TL);
}

// round 17
// speedup vs baseline: 1.2064x; 1.2064x over previous
#include <cuda_runtime.h>

// ---------------------------------------------------------------------------
// GRU encoder-decoder, persistent per-CTA recurrence, f32x2-packed compute.
// R15 = R13 (best: 3329us) + riskless latency tweaks:
//   * epilogue h_old loads hoisted ABOVE the h k-loop (off the critical tail)
//   * h k-loop unroll 8 -> 16 (deeper LDS software-pipelining window)
// Tiling: 4 units x 2 rows per thread, NT=256. Activations plain [k][32].
// Weights rz/n split (3x LDS.128/k, broadcast). tanh.approx epilogue.
// ---------------------------------------------------------------------------

typedef unsigned long long u64;

#define Hh     64
#define G3     192
#define ROWS   32
#define NT     256
#define TSEQ   256
#define NINP   6

// SMEM float offsets
#define OFF_WX0RZ  0        // [6][128]
#define OFF_WX0N   768      // [6][64]
#define OFF_WH0RZ  1152     // [64][128]
#define OFF_WH0N   9344     // [64][64]
#define OFF_WX1RZ  13440    // [64][128]
#define OFF_WX1N   21632    // [64][64]
#define OFF_WH1RZ  25728    // [64][128]
#define OFF_WH1N   33920    // [64][64]
#define OFF_HS0    38016    // [2][64][32]
#define OFF_HS1    42112    // [2][64][32]
#define OFF_XS     46208    // [2][8][32]
#define OFF_OW     46720    // [64]
#define OFF_OB     46784    // [1]
#define SMEM_FLOATS 46788   // 187,152 bytes

#define HBUF 2048
#define XBUF 256

__device__ __forceinline__ u64 pk2(float lo, float hi) {
    u64 r; asm("mov.b64 %0, {%1,%2};" : "=l"(r) : "f"(lo), "f"(hi)); return r;
}
__device__ __forceinline__ float2 up2(u64 v) {
    float2 r; asm("mov.b64 {%0,%1}, %2;" : "=f"(r.x), "=f"(r.y) : "l"(v)); return r;
}
#define FFMA2(acc, a, b) \
    asm("fma.rn.f32x2 %0, %1, %2, %0;" : "+l"(acc) : "l"(a), "l"(b))

__device__ __forceinline__ float tanhapx(float x) {
    float y; asm("tanh.approx.f32 %0, %1;" : "=f"(y) : "f"(x)); return y;
}
__device__ __forceinline__ float sigapx(float x) {
    return fmaf(tanhapx(0.5f * x), 0.5f, 0.5f);
}

// Split-transpose W[192][K] (row-major) into 4-unit-group layout:
//   rz[k*128 + ug*8 + (lane>>1)*4 + gate*2 + (lane&1)]   gates r(0),z(1)
//   n [k*64  + ug*4 + lane]                              gate n
__device__ __forceinline__ void load_w_split4(float* dstRZ, float* dstN,
                                              const float* __restrict__ src,
                                              int K, int tid) {
    for (int idx = tid; idx < G3 * K; idx += NT) {
        int g = idx / K;
        int k = idx - g * K;
        int gate = g >> 6;          // 0=r,1=z,2=n
        int j    = g & 63;
        int ug   = j >> 2;
        int lane = j & 3;
        float v = src[idx];
        if (gate < 2)
            dstRZ[k * 128 + ug * 8 + (lane >> 1) * 4 + gate * 2 + (lane & 1)] = v;
        else
            dstN [k * 64  + ug * 4 + lane] = v;
    }
}

// GRU cell for this thread's [4 units (2 f32x2 pairs) x 2 rows] tile.
// xsrc/hsrc/hdst plain [k][32]: value(k,row) at k*32+row.
template<int KIN>
__device__ __forceinline__ void gru_tile4(
    const float* __restrict__ Wxrz, const float* __restrict__ Wxn,
    const float* __restrict__ Whrz, const float* __restrict__ Whn,
    const float* __restrict__ xsrc, const float* __restrict__ hsrc,
    float* __restrict__ hdst,
    const u64 br[2], const u64 bz[2], const u64 bi[2], const u64 bh[2],
    int ug, int rt)
{
    const int j0 = ug * 4;

    // Hoisted h_old loads: issued before the k-loops so their latency is
    // covered by compute instead of sitting on the epilogue critical path.
    float2 ho[4];
#pragma unroll
    for (int u = 0; u < 4; u++)
        ho[u] = *(const float2*)(hsrc + (j0 + u) * 32 + 2 * rt);

    // accum[pair][row]
    u64 ar[2][2], az[2][2], ai[2][2], ah[2][2];
#pragma unroll
    for (int p = 0; p < 2; p++)
#pragma unroll
        for (int rr = 0; rr < 2; rr++) {
            ar[p][rr] = br[p]; az[p][rr] = bz[p];
            ai[p][rr] = bi[p]; ah[p][rr] = bh[p];
        }

    const float* wxrz = Wxrz + ug * 8;
    const float* wxn  = Wxn  + ug * 4;
    const float* xp   = xsrc + 2 * rt;
#pragma unroll
    for (int k = 0; k < KIN; k++) {
        float2 xv = *(const float2*)(xp + k * 32);
        ulonglong2 w01 = *(const ulonglong2*)(wxrz + k * 128);      // (r01, z01)
        ulonglong2 w23 = *(const ulonglong2*)(wxrz + k * 128 + 4);  // (r23, z23)
        ulonglong2 wn2 = *(const ulonglong2*)(wxn + k * 64);        // (n01, n23)
        u64 x0 = pk2(xv.x, xv.x), x1 = pk2(xv.y, xv.y);
        FFMA2(ar[0][0], w01.x, x0); FFMA2(ar[0][1], w01.x, x1);
        FFMA2(az[0][0], w01.y, x0); FFMA2(az[0][1], w01.y, x1);
        FFMA2(ar[1][0], w23.x, x0); FFMA2(ar[1][1], w23.x, x1);
        FFMA2(az[1][0], w23.y, x0); FFMA2(az[1][1], w23.y, x1);
        FFMA2(ai[0][0], wn2.x, x0); FFMA2(ai[0][1], wn2.x, x1);
        FFMA2(ai[1][0], wn2.y, x0); FFMA2(ai[1][1], wn2.y, x1);
    }

    const float* whrz = Whrz + ug * 8;
    const float* whn  = Whn  + ug * 4;
    const float* hp   = hsrc + 2 * rt;
#pragma unroll 16
    for (int k = 0; k < Hh; k++) {
        float2 hv = *(const float2*)(hp + k * 32);
        ulonglong2 w01 = *(const ulonglong2*)(whrz + k * 128);      // (r01, z01)
        ulonglong2 w23 = *(const ulonglong2*)(whrz + k * 128 + 4);  // (r23, z23)
        ulonglong2 wn2 = *(const ulonglong2*)(whn + k * 64);        // (n01, n23)
        u64 h0 = pk2(hv.x, hv.x), h1 = pk2(hv.y, hv.y);
        FFMA2(ar[0][0], w01.x, h0); FFMA2(ar[0][1], w01.x, h1);
        FFMA2(az[0][0], w01.y, h0); FFMA2(az[0][1], w01.y, h1);
        FFMA2(ar[1][0], w23.x, h0); FFMA2(ar[1][1], w23.x, h1);
        FFMA2(az[1][0], w23.y, h0); FFMA2(az[1][1], w23.y, h1);
        FFMA2(ah[0][0], wn2.x, h0); FFMA2(ah[0][1], wn2.x, h1);
        FFMA2(ah[1][0], wn2.y, h0); FFMA2(ah[1][1], wn2.y, h1);
    }

    // epilogue: r,z sigmoid; n = tanh(in + r*hn); h' = n + z*(h_old - n)
    float2 onew[4];
#pragma unroll
    for (int p = 0; p < 2; p++)
#pragma unroll
        for (int rr = 0; rr < 2; rr++) {
            float2 arv = up2(ar[p][rr]), azv = up2(az[p][rr]);
            float2 aiv = up2(ai[p][rr]), ahv = up2(ah[p][rr]);
            {
                float r = sigapx(arv.x), z = sigapx(azv.x);
                float n = tanhapx(fmaf(r, ahv.x, aiv.x));
                float hold = (rr == 0) ? ho[2 * p].x : ho[2 * p].y;
                float o = fmaf(z, hold - n, n);
                if (rr == 0) onew[2 * p].x = o; else onew[2 * p].y = o;
            }
            {
                float r = sigapx(arv.y), z = sigapx(azv.y);
                float n = tanhapx(fmaf(r, ahv.y, aiv.y));
                float hold = (rr == 0) ? ho[2 * p + 1].x : ho[2 * p + 1].y;
                float o = fmaf(z, hold - n, n);
                if (rr == 0) onew[2 * p + 1].x = o; else onew[2 * p + 1].y = o;
            }
        }
#pragma unroll
    for (int u = 0; u < 4; u++)
        *(float2*)(hdst + (j0 + u) * 32 + 2 * rt) = onew[u];
}

extern __shared__ float sm[];

__global__ __launch_bounds__(NT, 1)
void gru_kernel(
    const float* __restrict__ x,
    const float* __restrict__ eWih0, const float* __restrict__ eWhh0,
    const float* __restrict__ ebih0, const float* __restrict__ ebhh0,
    const float* __restrict__ eWih1, const float* __restrict__ eWhh1,
    const float* __restrict__ ebih1, const float* __restrict__ ebhh1,
    const float* __restrict__ dWih0, const float* __restrict__ dWhh0,
    const float* __restrict__ dbih0, const float* __restrict__ dbhh0,
    const float* __restrict__ dWih1, const float* __restrict__ dWhh1,
    const float* __restrict__ dbih1, const float* __restrict__ dbhh1,
    const float* __restrict__ outW, const float* __restrict__ outb,
    float* __restrict__ out, int Bn, int TL)
{
    const int tid = threadIdx.x;
    const int b0  = blockIdx.x * ROWS;

    float* Wx0rz = sm + OFF_WX0RZ;  float* Wx0n = sm + OFF_WX0N;
    float* Wh0rz = sm + OFF_WH0RZ;  float* Wh0n = sm + OFF_WH0N;
    float* Wx1rz = sm + OFF_WX1RZ;  float* Wx1n = sm + OFF_WX1N;
    float* Wh1rz = sm + OFF_WH1RZ;  float* Wh1n = sm + OFF_WH1N;
    float* hs0 = sm + OFF_HS0;
    float* hs1 = sm + OFF_HS1;
    float* xs  = sm + OFF_XS;
    float* sOW = sm + OFF_OW;
    float* sOB = sm + OFF_OB;

    const int rt = tid & 15;         // row tile (rows 2rt, 2rt+1)
    const int ug = tid >> 4;         // unit group (4 units)
    const int j0 = ug * 4;

    // ---- stage encoder weights ----
    load_w_split4(Wx0rz, Wx0n, eWih0, NINP, tid);
    load_w_split4(Wh0rz, Wh0n, eWhh0, Hh, tid);
    load_w_split4(Wx1rz, Wx1n, eWih1, Hh, tid);
    load_w_split4(Wh1rz, Wh1n, eWhh1, Hh, tid);
    for (int i = tid; i < HBUF; i += NT) {
        hs0[i] = 0.0f; hs0[HBUF + i] = 0.0f;
        hs1[i] = 0.0f; hs1[HBUF + i] = 0.0f;
    }

    // ---- encoder bias pairs in registers ----
    u64 e0r[2], e0z[2], e0i[2], e0h[2], e1r[2], e1z[2], e1i[2], e1h[2];
#pragma unroll
    for (int p = 0; p < 2; p++) {
        int jj = j0 + 2 * p;
        float2 a, b;
        a = *(const float2*)(ebih0 + jj);        b = *(const float2*)(ebhh0 + jj);
        e0r[p] = pk2(a.x + b.x, a.y + b.y);
        a = *(const float2*)(ebih0 + 64 + jj);   b = *(const float2*)(ebhh0 + 64 + jj);
        e0z[p] = pk2(a.x + b.x, a.y + b.y);
        a = *(const float2*)(ebih0 + 128 + jj);  e0i[p] = pk2(a.x, a.y);
        b = *(const float2*)(ebhh0 + 128 + jj);  e0h[p] = pk2(b.x, b.y);
        a = *(const float2*)(ebih1 + jj);        b = *(const float2*)(ebhh1 + jj);
        e1r[p] = pk2(a.x + b.x, a.y + b.y);
        a = *(const float2*)(ebih1 + 64 + jj);   b = *(const float2*)(ebhh1 + 64 + jj);
        e1z[p] = pk2(a.x + b.x, a.y + b.y);
        a = *(const float2*)(ebih1 + 128 + jj);  e1i[p] = pk2(a.x, a.y);
        b = *(const float2*)(ebhh1 + 128 + jj);  e1h[p] = pk2(b.x, b.y);
    }

    // prestage x for t=0 into buffer 0 ([k][32])
    const int xi = tid >> 5, xr = tid & 31;
    if (tid < NINP * ROWS) {
        float v = (b0 + xr < Bn)
            ? x[(size_t)(b0 + xr) * (TSEQ * NINP) + xi] : 0.0f;
        xs[xi * 32 + xr] = v;
    }
    __syncthreads();

    // ---- encoder: 256 steps ----
    int cur = 0;
    for (int t = 0; t < TSEQ; t++) {
        float xreg = 0.0f;
        if (tid < NINP * ROWS && t + 1 < TSEQ && b0 + xr < Bn)
            xreg = x[(size_t)(b0 + xr) * (TSEQ * NINP) + (size_t)(t + 1) * NINP + xi];
        int nxt = cur ^ 1;
        gru_tile4<NINP>(Wx0rz, Wx0n, Wh0rz, Wh0n,
                        xs + cur * XBUF, hs0 + cur * HBUF, hs0 + nxt * HBUF,
                        e0r, e0z, e0i, e0h, ug, rt);
        if (tid < NINP * ROWS) xs[nxt * XBUF + xi * 32 + xr] = xreg;
        __syncthreads();
        gru_tile4<Hh>(Wx1rz, Wx1n, Wh1rz, Wh1n,
                      hs0 + nxt * HBUF, hs1 + cur * HBUF, hs1 + nxt * HBUF,
                      e1r, e1z, e1i, e1h, ug, rt);
        cur = nxt;
        __syncthreads();
    }

    // ---- swap in decoder weights ----
    load_w_split4(Wx0rz, Wx0n, dWih0, 1, tid);
    load_w_split4(Wh0rz, Wh0n, dWhh0, Hh, tid);
    load_w_split4(Wx1rz, Wx1n, dWih1, Hh, tid);
    load_w_split4(Wh1rz, Wh1n, dWhh1, Hh, tid);
    if (tid < Hh) sOW[tid] = outW[tid];
    if (tid == 0) sOB[0] = outb[0];
    if (tid < ROWS) xs[tid] = 0.0f;      // prev cv = 0 at k=0
#pragma unroll
    for (int p = 0; p < 2; p++) {
        int jj = j0 + 2 * p;
        float2 a, b;
        a = *(const float2*)(dbih0 + jj);        b = *(const float2*)(dbhh0 + jj);
        e0r[p] = pk2(a.x + b.x, a.y + b.y);
        a = *(const float2*)(dbih0 + 64 + jj);   b = *(const float2*)(dbhh0 + 64 + jj);
        e0z[p] = pk2(a.x + b.x, a.y + b.y);
        a = *(const float2*)(dbih0 + 128 + jj);  e0i[p] = pk2(a.x, a.y);
        b = *(const float2*)(dbhh0 + 128 + jj);  e0h[p] = pk2(b.x, b.y);
        a = *(const float2*)(dbih1 + jj);        b = *(const float2*)(dbhh1 + jj);
        e1r[p] = pk2(a.x + b.x, a.y + b.y);
        a = *(const float2*)(dbih1 + 64 + jj);   b = *(const float2*)(dbhh1 + 64 + jj);
        e1z[p] = pk2(a.x + b.x, a.y + b.y);
        a = *(const float2*)(dbih1 + 128 + jj);  e1i[p] = pk2(a.x, a.y);
        b = *(const float2*)(dbhh1 + 128 + jj);  e1h[p] = pk2(b.x, b.y);
    }
    __syncthreads();

    // ---- decoder: TL autoregressive steps ----
    for (int s = 0; s < TL; s++) {
        int nxt = cur ^ 1;
        gru_tile4<1>(Wx0rz, Wx0n, Wh0rz, Wh0n,
                     xs, hs0 + cur * HBUF, hs0 + nxt * HBUF,
                     e0r, e0z, e0i, e0h, ug, rt);
        __syncthreads();
        gru_tile4<Hh>(Wx1rz, Wx1n, Wh1rz, Wh1n,
                      hs0 + nxt * HBUF, hs1 + cur * HBUF, hs1 + nxt * HBUF,
                      e1r, e1z, e1i, e1h, ug, rt);
        __syncthreads();
        if (tid < ROWS) {
            float acc = sOB[0];
            const float* hp = hs1 + nxt * HBUF + tid;
            #pragma unroll 8
            for (int j = 0; j < Hh; j++)
                acc = fmaf(sOW[j], hp[j * 32], acc);
            if (b0 + tid < Bn)
                out[(size_t)(b0 + tid) * TL + s] = acc;
            xs[tid] = acc;
        }
        cur = nxt;
        __syncthreads();
    }
}

extern "C" void kernel_launch(void* const* d_in, const int* in_sizes, int n_in,
                              void* d_out, int out_size) {
    const float* x      = (const float*)d_in[0];
    const float* eWih0  = (const float*)d_in[1];
    const float* eWhh0  = (const float*)d_in[2];
    const float* ebih0  = (const float*)d_in[3];
    const float* ebhh0  = (const float*)d_in[4];
    const float* eWih1  = (const float*)d_in[5];
    const float* eWhh1  = (const float*)d_in[6];
    const float* ebih1  = (const float*)d_in[7];
    const float* ebhh1  = (const float*)d_in[8];
    const float* dWih0  = (const float*)d_in[9];
    const float* dWhh0  = (const float*)d_in[10];
    const float* dbih0  = (const float*)d_in[11];
    const float* dbhh0  = (const float*)d_in[12];
    const float* dWih1  = (const float*)d_in[13];
    const float* dWhh1  = (const float*)d_in[14];
    const float* dbih1  = (const float*)d_in[15];
    const float* dbhh1  = (const float*)d_in[16];
    const float* outW   = (const float*)d_in[17];
    const float* outb   = (const float*)d_in[18];

    int B  = in_sizes[0] / (TSEQ * NINP);
    int TL = out_size / B;                       // 180
    int grid = (B + ROWS - 1) / ROWS;            // 128
    size_t smem = SMEM_FLOATS * sizeof(float);   // ~187 KB

    cudaFuncSetAttribute(gru_kernel,
                         cudaFuncAttributeMaxDynamicSharedMemorySize,
                         (int)smem);

    gru_kernel<<<grid, NT, smem>>>(
        x, eWih0, eWhh0, ebih0, ebhh0, eWih1, eWhh1, ebih1, ebhh1,
        dWih0, dWhh0, dbih0, dbhh0, dWih1, dWhh1, dbih1, dbhh1,
        outW, outb, (float*)d_out, B, TL);
}